// round 5
// baseline (speedup 1.0000x reference)
#include <cuda_runtime.h>
#include <cuda_fp16.h>
#include <math.h>
#include <stdint.h>

// ---------------- problem constants ----------------
#define Bb   256
#define Ss   32
#define VFd  512
#define IFd  256
#define Ff   768
#define Hh   1024
#define Ll   2
#define Kk   8
#define MB   (Ll*Bb)
#define G3F  (3*Ff)

// ---------------- GEMM tiling ----------------
#define BM 64
#define BN 64
#define BK 32
#define ROWB   80
#define PLANE  (64*ROWB)
#define STAGE_BYTES (2*PLANE)
#define NSTAGE 4
#define SMEM_TOTAL (NSTAGE*STAGE_BYTES)  // 40960

// ---------------- persistent device scratch ----------------
__device__ __align__(16) float g_dt  [Ss*Bb];
__device__ __align__(16) float g_Y   [MB*Ff];
__device__ __align__(16) __half g_Yh [MB*Ff];
__device__ __align__(16) __half g_xh [Ss*Bb*Ff];
__device__ __align__(16) __half g_h1 [MB*Hh];
__device__ __align__(16) __half g_h2 [MB*Hh];
__device__ __align__(16) __half g_x1h[Bb*Ff];
__device__ __align__(16) __half g_out[Ss*Bb*Ff];
__device__ __align__(16) float g_gx0 [Ss*Bb*G3F];
__device__ __align__(16) float g_gh0 [Bb*G3F];
__device__ __align__(16) float g_gh1 [Bb*G3F];
__device__ __align__(16) float g_gx1 [Bb*G3F];
__device__ __align__(16) float g_hid [Ss*Bb*128];
// fp16 weights
__device__ __align__(16) __half g_W0[Hh*Ff];
__device__ __align__(16) __half g_W1[Hh*Hh];
__device__ __align__(16) __half g_W2[Ff*Hh];
__device__ __align__(16) __half g_Wx[Ll*G3F*Ff];
__device__ __align__(16) __half g_Wh[Ll*G3F*Ff];
__device__ __align__(16) __half g_rW1c[128*Ff];
// barriers
__device__ unsigned g_rowcnt[8];
__device__ unsigned g_gridcnt;

__device__ __forceinline__ uint32_t smem_u32(const void* p) {
    uint32_t a;
    asm("{ .reg .u64 t; cvta.to.shared.u64 t, %1; cvt.u32.u64 %0, t; }" : "=r"(a) : "l"(p));
    return a;
}
__device__ __forceinline__ void cp16(uint32_t dst, const void* src) {
    asm volatile("cp.async.cg.shared.global [%0], [%1], 16;" :: "r"(dst), "l"(src));
}
__device__ __forceinline__ void ldm_x4(uint32_t addr, uint32_t r[4]) {
    asm volatile("ldmatrix.sync.aligned.m8n8.x4.shared.b16 {%0,%1,%2,%3}, [%4];"
                 : "=r"(r[0]), "=r"(r[1]), "=r"(r[2]), "=r"(r[3]) : "r"(addr));
}
__device__ __forceinline__ void mma16816(float d[4], const uint32_t a[4],
                                         uint32_t b0, uint32_t b1) {
    asm volatile("mma.sync.aligned.m16n8k16.row.col.f32.f16.f16.f32 "
                 "{%0,%1,%2,%3}, {%4,%5,%6,%7}, {%8,%9}, {%0,%1,%2,%3};"
                 : "+f"(d[0]), "+f"(d[1]), "+f"(d[2]), "+f"(d[3])
                 : "r"(a[0]), "r"(a[1]), "r"(a[2]), "r"(a[3]), "r"(b0), "r"(b1));
}

// global barrier: counter never decremented within a launch; zeroed by prep kernel
__device__ __forceinline__ void bar_wait(unsigned* ctr, unsigned target) {
    __syncthreads();
    if (threadIdx.x == 0) {
        __threadfence();
        atomicAdd(ctr, 1u);
        unsigned v;
        do {
            asm volatile("ld.acquire.gpu.u32 %0, [%1];" : "=r"(v) : "l"(ctr) : "memory");
        } while (v < target);
        __threadfence();
    }
    __syncthreads();
}

// ---------------- shared GEMM tile routine ----------------
// C[m0:+64, n0:+64] = epi(A[m0:,:K] * B[n0:,:K]^T + bias[n0:])
enum { EPI_STORE = 0, EPI_TANH = 1, EPI_ODE = 2, EPI_LRELU = 3 };

__device__ __noinline__ void gemm_tile(
    const __half* __restrict__ A, int lda,
    const __half* __restrict__ Bm, int ldb,
    const float* __restrict__ bias,
    int m0, int n0, int Kd, int epi,
    float* __restrict__ Cf, __half* __restrict__ Ch,
    int ldc, const float* __restrict__ dtv)
{
    extern __shared__ char smem[];
    const uint32_t smem_base = smem_u32(smem);
    const int tid  = threadIdx.x;
    const int wid  = tid >> 5, lane = tid & 31;
    const int warp_m = wid & 1, warp_n = wid >> 1;

    const int l_row0 = tid >> 2;
    const int l_kq   = (tid & 3) * 8;

    auto issue_stage = [&](int c) {
        const int k0 = c * BK;
        const uint32_t sb = smem_base + (uint32_t)(c % NSTAGE) * STAGE_BYTES;
#pragma unroll
        for (int i = 0; i < 2; i++) {
            const int row = l_row0 + i * 32;
            const uint32_t dst = sb + (uint32_t)row * ROWB + l_kq * 2;
            cp16(dst,         A  + (size_t)(m0 + row) * lda + k0 + l_kq);
            cp16(dst + PLANE, Bm + (size_t)(n0 + row) * ldb + k0 + l_kq);
        }
        asm volatile("cp.async.commit_group;");
    };

    float acc[2][4][4];
#pragma unroll
    for (int mi = 0; mi < 2; mi++)
#pragma unroll
        for (int nj = 0; nj < 4; nj++)
#pragma unroll
            for (int e = 0; e < 4; e++) acc[mi][nj][e] = 0.0f;

    const int nc = Kd / BK;
    issue_stage(0);
    issue_stage(1);
    if (nc > 2) issue_stage(2);

    const int arow  = lane & 15, acol8 = (lane >> 4) * 8;
    const int brow  = ((lane >> 4) & 1) * 8 + (lane & 7);
    const int bcol8 = ((lane >> 3) & 1) * 8;
    const uint32_t aoff = (uint32_t)(warp_m*32 + arow) * ROWB + acol8 * 2;
    const uint32_t boff = PLANE + (uint32_t)(warp_n*32 + brow) * ROWB + bcol8 * 2;

    for (int c = 0; c < nc; c++) {
        if (c + 2 < nc)      { asm volatile("cp.async.wait_group 2;"); }
        else if (c + 1 < nc) { asm volatile("cp.async.wait_group 1;"); }
        else                 { asm volatile("cp.async.wait_group 0;"); }
        __syncthreads();
        if (c + 3 < nc) issue_stage(c + 3);

        const uint32_t sb = smem_base + (uint32_t)(c % NSTAGE) * STAGE_BYTES;
#pragma unroll
        for (int kk = 0; kk < 2; kk++) {
            uint32_t ah[2][4], bh[2][4];
#pragma unroll
            for (int mi = 0; mi < 2; mi++)
                ldm_x4(sb + aoff + mi*16*ROWB + kk*32, ah[mi]);
#pragma unroll
            for (int nj = 0; nj < 2; nj++)
                ldm_x4(sb + boff + nj*16*ROWB + kk*32, bh[nj]);
#pragma unroll
            for (int mi = 0; mi < 2; mi++)
#pragma unroll
                for (int n8 = 0; n8 < 4; n8++) {
                    const int nj = n8 >> 1, hf = (n8 & 1) << 1;
                    mma16816(acc[mi][n8], ah[mi], bh[nj][hf], bh[nj][hf+1]);
                }
        }
        __syncthreads();
    }

    const int rbase = lane >> 2;
    const int cbase = (lane & 3) * 2;
#pragma unroll
    for (int mi = 0; mi < 2; mi++) {
#pragma unroll
        for (int n8 = 0; n8 < 4; n8++) {
#pragma unroll
            for (int half = 0; half < 2; half++) {
                const int m = m0 + warp_m*32 + mi*16 + rbase + half*8;
                const int n = n0 + warp_n*32 + n8*8 + cbase;
                float v0 = acc[mi][n8][half*2 + 0] + __ldg(bias + n);
                float v1 = acc[mi][n8][half*2 + 1] + __ldg(bias + n + 1);
                const size_t o = (size_t)m * ldc + n;
                if (epi == EPI_TANH) {
                    v0 = tanhf(v0); v1 = tanhf(v1);
                    *(__half2*)(Ch + o) = __floats2half2_rn(v0, v1);
                } else if (epi == EPI_ODE) {
                    const float sub = __ldg(dtv + (m & (Bb - 1))) * (1.0f / Kk);
                    float2 y = *(float2*)(Cf + o);
                    y.x += sub * v0; y.y += sub * v1;
                    *(float2*)(Cf + o) = y;
                    *(__half2*)(Ch + o) = __floats2half2_rn(y.x, y.y);
                } else if (epi == EPI_LRELU) {
                    v0 = (v0 > 0.f) ? v0 : 0.1f*v0;
                    v1 = (v1 > 0.f) ? v1 : 0.1f*v1;
                    *(float2*)(Cf + o) = make_float2(v0, v1);
                } else {
                    *(float2*)(Cf + o) = make_float2(v0, v1);
                }
            }
        }
    }
}

// GRU elementwise combine, spread across the whole grid
__device__ __forceinline__ void gru_combine(
    const float* __restrict__ gx, const float* __restrict__ gh,
    float* __restrict__ h, __half* __restrict__ hh, __half* __restrict__ xh)
{
    const int stride = gridDim.x * blockDim.x;
    for (int idx = blockIdx.x*blockDim.x + threadIdx.x; idx < Bb*Ff; idx += stride) {
        int b = idx / Ff, f = idx % Ff;
        int o = b*G3F + f;
        float r  = 1.0f / (1.0f + expf(-(gx[o]        + gh[o]       )));
        float z  = 1.0f / (1.0f + expf(-(gx[o + Ff]   + gh[o + Ff]  )));
        float n  = tanhf(gx[o + 2*Ff] + r * gh[o + 2*Ff]);
        float hn = (1.0f - z) * n + z * h[idx];
        h[idx] = hn;
        __half hv = __float2half_rn(hn);
        hh[idx] = hv;
        xh[idx] = hv;
    }
}

// ---------------- persistent sequence kernel ----------------
__global__ void __launch_bounds__(128)
k_seq(const float* __restrict__ b0, const float* __restrict__ b1,
      const float* __restrict__ b2o, const float* __restrict__ gbx,
      const float* __restrict__ gbh)
{
    const int mb = blockIdx.x >> 4;   // 0..7 (row-block of 64 in 512)
    const int nb = blockIdx.x & 15;   // 0..15
    unsigned row_epoch = 0, grid_epoch = 0;

    for (int t = 0; t < Ss; t++) {
        const float* dtv = g_dt + t*Bb;
        for (int k = 0; k < Kk; k++) {
            gemm_tile(g_Yh, Ff, g_W0, Ff, b0, mb*64, nb*64, Ff,
                      EPI_TANH, nullptr, g_h1, Hh, nullptr);
            bar_wait(&g_rowcnt[mb], (++row_epoch) * 16);
            gemm_tile(g_h1, Hh, g_W1, Hh, b1, mb*64, nb*64, Hh,
                      EPI_TANH, nullptr, g_h2, Hh, nullptr);
            bar_wait(&g_rowcnt[mb], (++row_epoch) * 16);
            if (nb < 12)
                gemm_tile(g_h2, Hh, g_W2, Hh, b2o, mb*64, nb*64, Hh,
                          EPI_ODE, g_Y, g_Yh, Ff, dtv);
            bar_wait(&g_rowcnt[mb], (++row_epoch) * 16);
        }
        bar_wait(&g_gridcnt, (++grid_epoch) * 128);

        // gh for both layers: 2 x (4 x 36) = 288 tiles
        for (int tile = blockIdx.x; tile < 288; tile += 128) {
            int layer = tile / 144, r = tile % 144;
            int mt = r / 36, nt = r % 36;
            gemm_tile(g_Yh + layer*Bb*Ff, Ff, g_Wh + (size_t)layer*G3F*Ff, Ff,
                      gbh + layer*G3F, mt*64, nt*64, Ff, EPI_STORE,
                      (layer ? g_gh1 : g_gh0), nullptr, G3F, nullptr);
        }
        bar_wait(&g_gridcnt, (++grid_epoch) * 128);

        gru_combine(g_gx0 + (size_t)t*Bb*G3F, g_gh0, g_Y, g_Yh, g_x1h);
        bar_wait(&g_gridcnt, (++grid_epoch) * 128);

        // gx1 = x1 @ Wx1^T : 4 x 36 = 144 tiles
        for (int tile = blockIdx.x; tile < 144; tile += 128) {
            int mt = tile / 36, nt = tile % 36;
            gemm_tile(g_x1h, Ff, g_Wx + (size_t)G3F*Ff, Ff, gbx + G3F,
                      mt*64, nt*64, Ff, EPI_STORE, g_gx1, nullptr, G3F, nullptr);
        }
        bar_wait(&g_gridcnt, (++grid_epoch) * 128);

        gru_combine(g_gx1, g_gh1, g_Y + Bb*Ff, g_Yh + Bb*Ff,
                    g_out + (size_t)t*Bb*Ff);
        bar_wait(&g_gridcnt, (++grid_epoch) * 128);
    }
}

// ---------------- standalone GEMM (prologue / epilogue GEMMs) ----------------
template<int EPI>
__global__ void __launch_bounds__(128)
k_mgemm(const __half* __restrict__ A, int lda,
        const __half* __restrict__ Bm, int ldb,
        const float* __restrict__ bias,
        float* __restrict__ Cf, __half* __restrict__ Ch,
        int ldc, int Kd, const float* __restrict__ dtv)
{
    gemm_tile(A, lda, Bm, ldb, bias, blockIdx.y*64, blockIdx.x*64, Kd,
              EPI, Cf, Ch, ldc, dtv);
}

// ---------------- prep kernels ----------------
__global__ void k_cvt(const float* __restrict__ src, __half* __restrict__ dst, int n) {
    int stride = gridDim.x * blockDim.x;
    for (int i = blockIdx.x*blockDim.x + threadIdx.x; i < n; i += stride)
        dst[i] = __float2half_rn(src[i]);
}

__global__ void k_prep_x(const float* __restrict__ fv, const float* __restrict__ fi) {
    int stride = gridDim.x * blockDim.x;
    int total  = Ss*Bb*Ff;
    for (int idx = blockIdx.x*blockDim.x + threadIdx.x; idx < total; idx += stride) {
        int f  = idx % Ff;
        int sb = idx / Ff;
        int b  = sb % Bb, s = sb / Bb;
        float v = (f < VFd) ? fv[(b*Ss + s)*VFd + f] : fi[(b*Ss + s)*IFd + (f - VFd)];
        g_xh[idx] = __float2half_rn(v);
    }
}

__global__ void k_prep_misc(const float* __restrict__ ts) {
    int stride = gridDim.x * blockDim.x;
    int gtid = blockIdx.x*blockDim.x + threadIdx.x;
    for (int i = gtid; i < MB*Ff; i += stride) {
        g_Y[i] = 0.0f; g_Yh[i] = __float2half(0.0f);
    }
    for (int i = gtid; i < Ss*Bb; i += stride) {
        int s = i / Bb, b = i % Bb;
        g_dt[i] = (s < Ss-1) ? (ts[b*Ss + s + 1] - ts[b*Ss + s]) : 0.0f;
    }
    if (gtid < 8) g_rowcnt[gtid] = 0;
    if (gtid == 8) g_gridcnt = 0;
}

// ---------------- regressor second layer (N=6) ----------------
__global__ void k_pose(const float* __restrict__ W2, const float* __restrict__ b2,
                       float* __restrict__ outp)
{
    int idx = blockIdx.x*blockDim.x + threadIdx.x;
    if (idx >= Ss*Bb*6) return;
    int n = idx % 6;
    int m = idx / 6;
    int b = m % Bb, s = m / Bb;
    const float* hrow = g_hid + (size_t)m * 128;
    const float* wrow = W2 + n * 128;
    float acc = b2[n];
#pragma unroll 8
    for (int k = 0; k < 128; k++) acc += hrow[k] * wrow[k];
    outp[(b*Ss + s)*6 + n] = acc;
}

__global__ void k_copyY(float* __restrict__ outp) {
    int stride = gridDim.x * blockDim.x;
    for (int i = blockIdx.x*blockDim.x + threadIdx.x; i < MB*Ff; i += stride)
        outp[i] = g_Y[i];
}

// ---------------- launch ----------------
extern "C" void kernel_launch(void* const* d_in, const int* in_sizes, int n_in,
                              void* d_out, int out_size)
{
    const float* fv  = (const float*)d_in[0];
    const float* fi  = (const float*)d_in[1];
    const float* ts  = (const float*)d_in[2];
    const float* W0  = (const float*)d_in[3];
    const float* b0  = (const float*)d_in[4];
    const float* W1  = (const float*)d_in[5];
    const float* b1  = (const float*)d_in[6];
    const float* W2o = (const float*)d_in[7];
    const float* b2o = (const float*)d_in[8];
    const float* gWx = (const float*)d_in[9];
    const float* gWh = (const float*)d_in[10];
    const float* gbx = (const float*)d_in[11];
    const float* gbh = (const float*)d_in[12];
    const float* rW1 = (const float*)d_in[13];
    const float* rb1 = (const float*)d_in[14];
    const float* rW2 = (const float*)d_in[15];
    const float* rb2 = (const float*)d_in[16];

    cudaFuncSetAttribute(k_mgemm<EPI_STORE>, cudaFuncAttributeMaxDynamicSharedMemorySize, SMEM_TOTAL);
    cudaFuncSetAttribute(k_mgemm<EPI_LRELU>, cudaFuncAttributeMaxDynamicSharedMemorySize, SMEM_TOTAL);
    cudaFuncSetAttribute(k_seq, cudaFuncAttributeMaxDynamicSharedMemorySize, SMEM_TOTAL);

#define SYM(p, s) float* p; cudaGetSymbolAddress((void**)&p, s)
#define SYMH(p, s) __half* p; cudaGetSymbolAddress((void**)&p, s)
    SYMH(pxh, g_xh); SYMH(pout, g_out);
    SYM(pgx0, g_gx0); SYM(phid, g_hid);
    SYMH(pW0, g_W0); SYMH(pW1, g_W1); SYMH(pW2, g_W2);
    SYMH(pWx, g_Wx); SYMH(pWh, g_Wh); SYMH(prW1, g_rW1c);
#undef SYM
#undef SYMH

    // weight conversions (deterministic; recomputed every call)
    k_cvt<<<256, 256>>>(W0,  pW0,  Hh*Ff);
    k_cvt<<<256, 256>>>(W1,  pW1,  Hh*Hh);
    k_cvt<<<256, 256>>>(W2o, pW2,  Ff*Hh);
    k_cvt<<<256, 256>>>(gWx, pWx,  Ll*G3F*Ff);
    k_cvt<<<256, 256>>>(gWh, pWh,  Ll*G3F*Ff);
    k_cvt<<<64,  256>>>(rW1, prW1, 128*Ff);

    k_prep_x<<<512, 256>>>(fv, fi);
    k_prep_misc<<<512, 256>>>(ts);

    // hoisted layer-0 GRU input projection: gx0[S*B,3F] = x @ Wx0^T + bx0
    k_mgemm<EPI_STORE><<<dim3(G3F/BN, (Ss*Bb)/BM), 128, SMEM_TOTAL>>>(
        pxh, Ff, pWx, Ff, gbx, pgx0, nullptr, G3F, Ff, nullptr);

    // the whole recurrence in one persistent kernel
    k_seq<<<128, 128, SMEM_TOTAL>>>(b0, b1, b2o, gbx, gbh);

    // regressor
    k_mgemm<EPI_LRELU><<<dim3(128/BN, (Ss*Bb)/BM), 128, SMEM_TOTAL>>>(
        pout, Ff, prW1, Ff, rb1, phid, nullptr, 128, Ff, nullptr);
    k_pose<<<(Ss*Bb*6 + 127)/128, 128>>>(rW2, rb2, (float*)d_out);

    if (out_size >= Ss*Bb*6 + MB*Ff)
        k_copyY<<<768, 256>>>((float*)d_out + Ss*Bb*6);
}

// round 6
// speedup vs baseline: 1.2745x; 1.2745x over previous
#include <cuda_runtime.h>
#include <cuda_fp16.h>
#include <math.h>
#include <stdint.h>

// ---------------- problem constants ----------------
#define Bb   256
#define Ss   32
#define VFd  512
#define IFd  256
#define Ff   768
#define Hh   1024
#define Ll   2
#define Kk   8
#define MB   (Ll*Bb)
#define G3F  (3*Ff)

// ---------------- GEMM tiling ----------------
#define BM 64
#define BN 64
#define BK 64
#define ROWB   144            // 64 halves = 128B data + 16B pad (conflict-free ldmatrix)
#define PLANE  (64*ROWB)      // 9216 B
#define STAGE_BYTES (2*PLANE) // 18432 B
#define NSTAGE 4
#define SMEM_TOTAL (NSTAGE*STAGE_BYTES)  // 73728

// ---------------- persistent device scratch ----------------
__device__ __align__(16) float g_dt  [Ss*Bb];
__device__ __align__(16) float g_Y   [MB*Ff];
__device__ __align__(16) __half g_Yh [MB*Ff];
__device__ __align__(16) __half g_xh [Ss*Bb*Ff];
__device__ __align__(16) __half g_h1 [MB*Hh];
__device__ __align__(16) __half g_h2 [MB*Hh];
__device__ __align__(16) __half g_x1h[Bb*Ff];
__device__ __align__(16) __half g_out[Ss*Bb*Ff];
__device__ __align__(16) float g_gx0 [Ss*Bb*G3F];
__device__ __align__(16) float g_gh  [2*Bb*G3F];   // layer 0 then layer 1
__device__ __align__(16) float g_gx1 [Bb*G3F];
__device__ __align__(16) float g_hid [Ss*Bb*128];
// fp16 weights
__device__ __align__(16) __half g_W0[Hh*Ff];
__device__ __align__(16) __half g_W1[Hh*Hh];
__device__ __align__(16) __half g_W2[Ff*Hh];
__device__ __align__(16) __half g_Wx[Ll*G3F*Ff];
__device__ __align__(16) __half g_Wh[Ll*G3F*Ff];
__device__ __align__(16) __half g_rW1c[128*Ff];

__device__ __forceinline__ uint32_t smem_u32(const void* p) {
    uint32_t a;
    asm("{ .reg .u64 t; cvta.to.shared.u64 t, %1; cvt.u32.u64 %0, t; }" : "=r"(a) : "l"(p));
    return a;
}
__device__ __forceinline__ void cp16(uint32_t dst, const void* src) {
    asm volatile("cp.async.cg.shared.global [%0], [%1], 16;" :: "r"(dst), "l"(src));
}
__device__ __forceinline__ void ldm_x4(uint32_t addr, uint32_t r[4]) {
    asm volatile("ldmatrix.sync.aligned.m8n8.x4.shared.b16 {%0,%1,%2,%3}, [%4];"
                 : "=r"(r[0]), "=r"(r[1]), "=r"(r[2]), "=r"(r[3]) : "r"(addr));
}
__device__ __forceinline__ void mma16816(float d[4], const uint32_t a[4],
                                         uint32_t b0, uint32_t b1) {
    asm volatile("mma.sync.aligned.m16n8k16.row.col.f32.f16.f16.f32 "
                 "{%0,%1,%2,%3}, {%4,%5,%6,%7}, {%8,%9}, {%0,%1,%2,%3};"
                 : "+f"(d[0]), "+f"(d[1]), "+f"(d[2]), "+f"(d[3])
                 : "r"(a[0]), "r"(a[1]), "r"(a[2]), "r"(a[3]), "r"(b0), "r"(b1));
}

// ---------------- core GEMM tile: 64x64, 256 threads (8 warps, 2x4) ----------------
enum { EPI_STORE = 0, EPI_TANH = 1, EPI_ODE = 2, EPI_LRELU = 3 };

template<int EPI>
__device__ __forceinline__ void gemm_core(
    const __half* __restrict__ A, int lda,
    const __half* __restrict__ Bm, int ldb,
    const float* __restrict__ bias,
    int m0, int n0, int Kd,
    float* __restrict__ Cf, __half* __restrict__ Ch,
    int ldc, const float* __restrict__ dtv)
{
    extern __shared__ char smem[];
    __shared__ float sbias[BN];
    const uint32_t smem_base = smem_u32(smem);
    const int tid  = threadIdx.x;
    const int wid  = tid >> 5, lane = tid & 31;
    const int warp_m = wid & 1;      // 0..1 -> 32 rows
    const int warp_n = wid >> 1;     // 0..3 -> 16 cols

    if (tid < BN) sbias[tid] = bias[n0 + tid];

    const int l_row = tid >> 2;           // 0..63 (with u = tid + i*256)
    const int l_c16a = tid & 3;           // chunk 0..3, then +4

    auto issue_stage = [&](int c) {
        const int k0 = c * BK;
        const uint32_t sb = smem_base + (uint32_t)(c % NSTAGE) * STAGE_BYTES;
#pragma unroll
        for (int i = 0; i < 2; i++) {
            const int c16 = l_c16a + i * 4;
            const uint32_t dst = sb + (uint32_t)l_row * ROWB + c16 * 16;
            cp16(dst,         A  + (size_t)(m0 + l_row) * lda + k0 + c16 * 8);
            cp16(dst + PLANE, Bm + (size_t)(n0 + l_row) * ldb + k0 + c16 * 8);
        }
        asm volatile("cp.async.commit_group;");
    };

    float acc[2][2][4];
#pragma unroll
    for (int mi = 0; mi < 2; mi++)
#pragma unroll
        for (int nj = 0; nj < 2; nj++)
#pragma unroll
            for (int e = 0; e < 4; e++) acc[mi][nj][e] = 0.0f;

    const int nc = Kd / BK;
    issue_stage(0);
    issue_stage(1);
    if (nc > 2) issue_stage(2);

    const int arow  = lane & 15, acol8 = (lane >> 4) * 8;
    const int brow  = ((lane >> 4) & 1) * 8 + (lane & 7);
    const int bcol8 = ((lane >> 3) & 1) * 8;
    const uint32_t aoff = (uint32_t)(warp_m*32 + arow) * ROWB + acol8 * 2;
    const uint32_t boff = PLANE + (uint32_t)(warp_n*16 + brow) * ROWB + bcol8 * 2;

    for (int c = 0; c < nc; c++) {
        if (c + 2 < nc)      { asm volatile("cp.async.wait_group 2;"); }
        else if (c + 1 < nc) { asm volatile("cp.async.wait_group 1;"); }
        else                 { asm volatile("cp.async.wait_group 0;"); }
        __syncthreads();
        if (c + 3 < nc) issue_stage(c + 3);

        const uint32_t sb = smem_base + (uint32_t)(c % NSTAGE) * STAGE_BYTES;
#pragma unroll
        for (int kk = 0; kk < 4; kk++) {
            uint32_t ah[2][4], bh[4];
#pragma unroll
            for (int mi = 0; mi < 2; mi++)
                ldm_x4(sb + aoff + mi*16*ROWB + kk*32, ah[mi]);
            ldm_x4(sb + boff + kk*32, bh);
#pragma unroll
            for (int mi = 0; mi < 2; mi++)
#pragma unroll
                for (int nj = 0; nj < 2; nj++)
                    mma16816(acc[mi][nj], ah[mi], bh[nj*2], bh[nj*2+1]);
        }
        __syncthreads();
    }

    const int rbase = lane >> 2;
    const int cbase = (lane & 3) * 2;
#pragma unroll
    for (int mi = 0; mi < 2; mi++) {
#pragma unroll
        for (int nj = 0; nj < 2; nj++) {
#pragma unroll
            for (int half = 0; half < 2; half++) {
                const int m  = m0 + warp_m*32 + mi*16 + rbase + half*8;
                const int nl = warp_n*16 + nj*8 + cbase;   // col within tile
                const int n  = n0 + nl;
                float v0 = acc[mi][nj][half*2 + 0] + sbias[nl];
                float v1 = acc[mi][nj][half*2 + 1] + sbias[nl + 1];
                const size_t o = (size_t)m * ldc + n;
                if (EPI == EPI_TANH) {
                    v0 = tanhf(v0); v1 = tanhf(v1);
                    *(__half2*)(Ch + o) = __floats2half2_rn(v0, v1);
                } else if (EPI == EPI_ODE) {
                    const float sub = __ldg(dtv + (m & (Bb - 1))) * (1.0f / Kk);
                    float2 y = *(float2*)(Cf + o);
                    y.x += sub * v0; y.y += sub * v1;
                    *(float2*)(Cf + o) = y;
                    *(__half2*)(Ch + o) = __floats2half2_rn(y.x, y.y);
                } else if (EPI == EPI_LRELU) {
                    v0 = (v0 > 0.f) ? v0 : 0.1f*v0;
                    v1 = (v1 > 0.f) ? v1 : 0.1f*v1;
                    *(float2*)(Cf + o) = make_float2(v0, v1);
                } else {
                    *(float2*)(Cf + o) = make_float2(v0, v1);
                }
            }
        }
    }
}

// ---------------- standalone GEMM kernels ----------------
template<int EPI>
__global__ void __launch_bounds__(256)
k_mgemm(const __half* __restrict__ A, int lda,
        const __half* __restrict__ Bm, int ldb,
        const float* __restrict__ bias,
        float* __restrict__ Cf, __half* __restrict__ Ch,
        int ldc, int Kd, const float* __restrict__ dtv)
{
    gemm_core<EPI>(A, lda, Bm, ldb, bias, blockIdx.y*64, blockIdx.x*64, Kd,
                   Cf, Ch, ldc, dtv);
}

// batched GRU hidden projection: z = layer (0,1)
__global__ void __launch_bounds__(256)
k_gh(const float* __restrict__ gbh)
{
    const int z = blockIdx.z;
    gemm_core<EPI_STORE>(g_Yh + (size_t)z*Bb*Ff, Ff,
                         g_Wh + (size_t)z*G3F*Ff, Ff,
                         gbh + z*G3F,
                         blockIdx.y*64, blockIdx.x*64, Ff,
                         g_gh + (size_t)z*Bb*G3F, nullptr, G3F, nullptr);
}

// ---------------- prep kernels ----------------
__global__ void k_cvt(const float* __restrict__ src, __half* __restrict__ dst, int n) {
    int stride = gridDim.x * blockDim.x;
    for (int i = blockIdx.x*blockDim.x + threadIdx.x; i < n; i += stride)
        dst[i] = __float2half_rn(src[i]);
}

__global__ void k_prep_x(const float* __restrict__ fv, const float* __restrict__ fi) {
    int stride = gridDim.x * blockDim.x;
    int total  = Ss*Bb*Ff;
    for (int idx = blockIdx.x*blockDim.x + threadIdx.x; idx < total; idx += stride) {
        int f  = idx % Ff;
        int sb = idx / Ff;
        int b  = sb % Bb, s = sb / Bb;
        float v = (f < VFd) ? fv[(b*Ss + s)*VFd + f] : fi[(b*Ss + s)*IFd + (f - VFd)];
        g_xh[idx] = __float2half_rn(v);
    }
}

__global__ void k_prep_misc(const float* __restrict__ ts) {
    int stride = gridDim.x * blockDim.x;
    int gtid = blockIdx.x*blockDim.x + threadIdx.x;
    for (int i = gtid; i < MB*Ff; i += stride) {
        g_Y[i] = 0.0f; g_Yh[i] = __float2half(0.0f);
    }
    for (int i = gtid; i < Ss*Bb; i += stride) {
        int s = i / Bb, b = i % Bb;
        g_dt[i] = (s < Ss-1) ? (ts[b*Ss + s + 1] - ts[b*Ss + s]) : 0.0f;
    }
}

// ---------------- GRU elementwise combine ----------------
__global__ void k_gru(const float* __restrict__ gx, const float* __restrict__ gh,
                      float* __restrict__ h, __half* __restrict__ hh,
                      __half* __restrict__ xh)
{
    int idx = blockIdx.x*blockDim.x + threadIdx.x;
    if (idx >= Bb*Ff) return;
    int b = idx / Ff, f = idx % Ff;
    int o = b*G3F + f;
    float r  = 1.0f / (1.0f + expf(-(gx[o]        + gh[o]       )));
    float z  = 1.0f / (1.0f + expf(-(gx[o + Ff]   + gh[o + Ff]  )));
    float n  = tanhf(gx[o + 2*Ff] + r * gh[o + 2*Ff]);
    float hn = (1.0f - z) * n + z * h[idx];
    h[idx] = hn;
    __half hv = __float2half_rn(hn);
    hh[idx] = hv;
    xh[idx] = hv;
}

// ---------------- regressor second layer (N=6) ----------------
__global__ void k_pose(const float* __restrict__ W2, const float* __restrict__ b2,
                       float* __restrict__ outp)
{
    int idx = blockIdx.x*blockDim.x + threadIdx.x;
    if (idx >= Ss*Bb*6) return;
    int n = idx % 6;
    int m = idx / 6;
    int b = m % Bb, s = m / Bb;
    const float* hrow = g_hid + (size_t)m * 128;
    const float* wrow = W2 + n * 128;
    float acc = b2[n];
#pragma unroll 8
    for (int k = 0; k < 128; k++) acc += hrow[k] * wrow[k];
    outp[(b*Ss + s)*6 + n] = acc;
}

__global__ void k_copyY(float* __restrict__ outp) {
    int stride = gridDim.x * blockDim.x;
    for (int i = blockIdx.x*blockDim.x + threadIdx.x; i < MB*Ff; i += stride)
        outp[i] = g_Y[i];
}

// ---------------- launch ----------------
extern "C" void kernel_launch(void* const* d_in, const int* in_sizes, int n_in,
                              void* d_out, int out_size)
{
    const float* fv  = (const float*)d_in[0];
    const float* fi  = (const float*)d_in[1];
    const float* ts  = (const float*)d_in[2];
    const float* W0  = (const float*)d_in[3];
    const float* b0  = (const float*)d_in[4];
    const float* W1  = (const float*)d_in[5];
    const float* b1  = (const float*)d_in[6];
    const float* W2o = (const float*)d_in[7];
    const float* b2o = (const float*)d_in[8];
    const float* gWx = (const float*)d_in[9];
    const float* gWh = (const float*)d_in[10];
    const float* gbx = (const float*)d_in[11];
    const float* gbh = (const float*)d_in[12];
    const float* rW1 = (const float*)d_in[13];
    const float* rb1 = (const float*)d_in[14];
    const float* rW2 = (const float*)d_in[15];
    const float* rb2 = (const float*)d_in[16];

    cudaFuncSetAttribute(k_mgemm<EPI_STORE>, cudaFuncAttributeMaxDynamicSharedMemorySize, SMEM_TOTAL);
    cudaFuncSetAttribute(k_mgemm<EPI_TANH >, cudaFuncAttributeMaxDynamicSharedMemorySize, SMEM_TOTAL);
    cudaFuncSetAttribute(k_mgemm<EPI_ODE  >, cudaFuncAttributeMaxDynamicSharedMemorySize, SMEM_TOTAL);
    cudaFuncSetAttribute(k_mgemm<EPI_LRELU>, cudaFuncAttributeMaxDynamicSharedMemorySize, SMEM_TOTAL);
    cudaFuncSetAttribute(k_gh, cudaFuncAttributeMaxDynamicSharedMemorySize, SMEM_TOTAL);

#define SYM(p, s) float* p; cudaGetSymbolAddress((void**)&p, s)
#define SYMH(p, s) __half* p; cudaGetSymbolAddress((void**)&p, s)
    SYM(pdt, g_dt); SYM(pY, g_Y);
    SYMH(pYh, g_Yh); SYMH(pxh, g_xh);
    SYMH(ph1, g_h1); SYMH(ph2, g_h2); SYMH(px1, g_x1h); SYMH(pout, g_out);
    SYM(pgx0, g_gx0); SYM(pgh, g_gh); SYM(pgx1, g_gx1); SYM(phid, g_hid);
    SYMH(pW0, g_W0); SYMH(pW1, g_W1); SYMH(pW2, g_W2);
    SYMH(pWx, g_Wx); SYMH(pWh, g_Wh); SYMH(prW1, g_rW1c);
#undef SYM
#undef SYMH

    // weight conversions (deterministic; recomputed every call)
    k_cvt<<<256, 256>>>(W0,  pW0,  Hh*Ff);
    k_cvt<<<256, 256>>>(W1,  pW1,  Hh*Hh);
    k_cvt<<<256, 256>>>(W2o, pW2,  Ff*Hh);
    k_cvt<<<256, 256>>>(gWx, pWx,  Ll*G3F*Ff);
    k_cvt<<<256, 256>>>(gWh, pWh,  Ll*G3F*Ff);
    k_cvt<<<64,  256>>>(rW1, prW1, 128*Ff);

    k_prep_x<<<512, 256>>>(fv, fi);
    k_prep_misc<<<512, 256>>>(ts);

    // hoisted layer-0 GRU input projection: gx0[S*B,3F] = x @ Wx0^T + bx0
    k_mgemm<EPI_STORE><<<dim3(G3F/BN, (Ss*Bb)/BM), 256, SMEM_TOTAL>>>(
        pxh, Ff, pWx, Ff, gbx, pgx0, nullptr, G3F, Ff, nullptr);

    const int gruBlocks = (Bb*Ff + 255) / 256;

    for (int t = 0; t < Ss; t++) {
        for (int k = 0; k < Kk; k++) {
            k_mgemm<EPI_TANH><<<dim3(Hh/BN, MB/BM), 256, SMEM_TOTAL>>>(
                pYh, Ff, pW0, Ff, b0, nullptr, ph1, Hh, Ff, nullptr);
            k_mgemm<EPI_TANH><<<dim3(Hh/BN, MB/BM), 256, SMEM_TOTAL>>>(
                ph1, Hh, pW1, Hh, b1, nullptr, ph2, Hh, Hh, nullptr);
            k_mgemm<EPI_ODE><<<dim3(Ff/BN, MB/BM), 256, SMEM_TOTAL>>>(
                ph2, Hh, pW2, Hh, b2o, pY, pYh, Ff, Hh, pdt + t*Bb);
        }
        // GRU hidden projections, both layers batched (pre-GRU state)
        k_gh<<<dim3(G3F/BN, Bb/BM, 2), 256, SMEM_TOTAL>>>(gbh);
        // GRU layer 0 combine
        k_gru<<<gruBlocks, 256>>>(pgx0 + (size_t)t*Bb*G3F, pgh, pY, pYh, px1);
        // GRU layer 1 input projection + combine
        k_mgemm<EPI_STORE><<<dim3(G3F/BN, Bb/BM), 256, SMEM_TOTAL>>>(
            px1, Ff, pWx + (size_t)G3F*Ff, Ff, gbx + G3F, pgx1, nullptr, G3F, Ff, nullptr);
        k_gru<<<gruBlocks, 256>>>(pgx1, pgh + (size_t)Bb*G3F, pY + Bb*Ff, pYh + Bb*Ff,
                                  pout + (size_t)t*Bb*Ff);
    }

    // regressor
    k_mgemm<EPI_LRELU><<<dim3(128/BN, (Ss*Bb)/BM), 256, SMEM_TOTAL>>>(
        pout, Ff, prW1, Ff, rb1, phid, nullptr, 128, Ff, nullptr);
    k_pose<<<(Ss*Bb*6 + 127)/128, 128>>>(rW2, rb2, (float*)d_out);

    if (out_size >= Ss*Bb*6 + MB*Ff)
        k_copyY<<<768, 256>>>((float*)d_out + Ss*Bb*6);
}